// round 13
// baseline (speedup 1.0000x reference)
#include <cuda_runtime.h>
#include <cuda_fp16.h>
#include <math.h>
#include <stdint.h>

// ---------------- problem constants ----------------
#define BATCH 512
#define HDIM  2048
#define BH    (BATCH * HDIM)       // 1,048,576
#define ACT   (BATCH * HDIM)
#define WELEM (2048 * 2048)
#define KTOT  4096

// ---------------- GEMM tiling (proven R10 config) ----------------
#define BM 128
#define BN 128
#define BK 32
#define NITER (KTOT / BK)          // 128

#define A_STRIDE 40
#define B_STRIDE 136
#define A_TILE_B (128 * A_STRIDE * 2)   // 10240 B
#define B_TILE_B (BK * B_STRIDE * 2)    // 8704 B
#define OFF_A 0
#define OFF_B (A_TILE_B)
#define STAGE_B (A_TILE_B + B_TILE_B)   // 18944
#define NSTAGE 4
#define DYN_SMEM (NSTAGE * STAGE_B)     // 75776

// producer-consumer
#define NGEMM 256
#define NCONV 40
#define NU_ACT 1024
#define NU (NU_ACT + 16384)        // 17408 units of 2048 elems

// ---------------- device scratch ----------------
__device__ float g_Z[4ull * BH];                 // 16 MB
__device__ __half g_A[2ull * ACT];               // [phase][B][2048] fp16
__device__ __half g_B[8ull * WELEM];             // [gate*2+phase][K][N] fp16
__device__ int g_wflag[128];                     // [mat 0..7][blk 0..15], target 128
__device__ int g_actsflag;                       // target 1024

// ---------------- PTX helpers ----------------
__device__ __forceinline__ uint32_t s2u(const void* p) {
    uint32_t a;
    asm("{ .reg .u64 t; cvta.to.shared.u64 t, %1; cvt.u32.u64 %0, t; }"
        : "=r"(a) : "l"(p));
    return a;
}
__device__ __forceinline__ void cp16(uint32_t dst, const void* src) {
    asm volatile("cp.async.cg.shared.global [%0], [%1], 16;" :: "r"(dst), "l"(src));
}
#define LDSM4(R, addr)                                                        \
    asm volatile("ldmatrix.sync.aligned.m8n8.x4.shared.b16 {%0,%1,%2,%3}, [%4];" \
                 : "=r"((R)[0]), "=r"((R)[1]), "=r"((R)[2]), "=r"((R)[3])     \
                 : "r"(addr))
#define LDSM4T(R, addr)                                                       \
    asm volatile("ldmatrix.sync.aligned.m8n8.x4.trans.shared.b16 {%0,%1,%2,%3}, [%4];" \
                 : "=r"((R)[0]), "=r"((R)[1]), "=r"((R)[2]), "=r"((R)[3])     \
                 : "r"(addr))
#define MMA(D, A, B0, B1)                                                     \
    asm volatile("mma.sync.aligned.m16n8k16.row.col.f32.f16.f16.f32 "          \
                 "{%0,%1,%2,%3},{%4,%5,%6,%7},{%8,%9},{%0,%1,%2,%3};"          \
                 : "+f"((D)[0]), "+f"((D)[1]), "+f"((D)[2]), "+f"((D)[3])     \
                 : "r"((A)[0]), "r"((A)[1]), "r"((A)[2]), "r"((A)[3]),        \
                   "r"(B0), "r"(B1))

__device__ __forceinline__ void wait_ge(const int* f, int t) {
    int v;
    asm volatile("ld.acquire.gpu.b32 %0, [%1];" : "=r"(v) : "l"(f));
    while (v < t) {
        __nanosleep(128);
        asm volatile("ld.acquire.gpu.b32 %0, [%1];" : "=r"(v) : "l"(f));
    }
}

__device__ __forceinline__ const float* mat_src(int mat,
    const float* Wi, const float* Ui, const float* Wf, const float* Uf,
    const float* Wg, const float* Ug, const float* Wc, const float* Uc) {
    switch (mat) {
        case 0: return Wi; case 1: return Ui;
        case 2: return Wf; case 3: return Uf;
        case 4: return Wg; case 5: return Ug;
        case 6: return Wc; default: return Uc;
    }
}

// ---------------- conversion unit helpers (2048 fp32 -> fp16, 128 thr) -----
__device__ __forceinline__ void unit_load(const float* __restrict__ src,
                                          int tid, float4* v) {
    const float4* p = reinterpret_cast<const float4*>(src) + tid * 4;
    v[0] = p[0]; v[1] = p[1]; v[2] = p[2]; v[3] = p[3];
}
__device__ __forceinline__ void unit_store(__half* __restrict__ dst,
                                           int tid, const float4* v) {
    __half2 h[8];
    #pragma unroll
    for (int i = 0; i < 4; i++) {
        h[2 * i]     = __floats2half2_rn(v[i].x, v[i].y);
        h[2 * i + 1] = __floats2half2_rn(v[i].z, v[i].w);
    }
    uint4* q = reinterpret_cast<uint4*>(dst) + tid * 2;
    q[0] = *reinterpret_cast<uint4*>(&h[0]);
    q[1] = *reinterpret_cast<uint4*>(&h[4]);
}

// deadline-ordered unit decode: acts, then phase-0 mats kb-major, then phase-1
__device__ __forceinline__ void unit_decode(int u,
        const float* X, const float* S,
        const float* Wi, const float* Ui, const float* Wf, const float* Uf,
        const float* Wg, const float* Ug, const float* Wc, const float* Uc,
        const float** src, __half** dst, int** flag) {
    if (u < NU_ACT) {
        *src = (u < 512) ? X + (size_t)u * 2048 : S + (size_t)(u - 512) * 2048;
        *dst = g_A + (size_t)u * 2048;
        *flag = &g_actsflag;
    } else {
        int q = u - NU_ACT;
        int ph = q >> 13;          // 0: phase-0 mats, 1: phase-1
        q &= 8191;
        int kb = q >> 7;           // 0..63
        int m4 = (q >> 5) & 3;     // 0..3
        int s  = q & 31;           // row-unit within kb
        int mat = m4 * 2 + ph;
        size_t off = (size_t)kb * 65536 + (size_t)s * 2048;
        *src = mat_src(mat, Wi, Ui, Wf, Uf, Wg, Ug, Wc, Uc) + off;
        *dst = g_B + (size_t)mat * WELEM + off;
        *flag = &g_wflag[mat * 16 + (kb >> 2)];
    }
}

// ---------------- GEMM tile prefetch (R10 verbatim) ----------------
__device__ __forceinline__ void prefetch(uint32_t stage, int tid,
                                         int gate, int bm, int bn, int c) {
    int k0 = c * BK;
    int phase = k0 >> 11;
    int kk = k0 & 2047;
    const __half* A_p = g_A + (size_t)phase * ACT + (size_t)bm * 2048 + kk;
    const __half* B_p = g_B + (size_t)(gate * 2 + phase) * WELEM
                            + (size_t)kk * 2048 + bn;

    #pragma unroll
    for (int t = 0; t < 4; t++) {
        int cid = tid + t * 128;
        int r = cid >> 2, cc = cid & 3;
        cp16(stage + OFF_A + (uint32_t)(r * (A_STRIDE * 2) + cc * 16),
             A_p + (size_t)r * 2048 + cc * 8);
    }
    #pragma unroll
    for (int t = 0; t < 4; t++) {
        int cid = tid + t * 128;
        int r = cid >> 4, cc = cid & 15;
        cp16(stage + OFF_B + (uint32_t)(r * (B_STRIDE * 2) + cc * 16),
             B_p + (size_t)r * 2048 + cc * 8);
    }
}

// ---------------- fused kernel: 256 GEMM CTAs + 40 converter CTAs ----------
__global__ __launch_bounds__(128, 2) void gemm_fused(
    const float* __restrict__ X, const float* __restrict__ S,
    const float* Wi, const float* Ui, const float* Wf, const float* Uf,
    const float* Wg, const float* Ug, const float* Wc, const float* Uc)
{
    extern __shared__ char smem[];
    const int tid = threadIdx.x;
    const int bid = blockIdx.x;

    // ================= converter CTAs =================
    if (bid >= NGEMM) {
        const int v = bid - NGEMM;   // 0..39
        #pragma unroll 1
        for (int i = v; i < NU; i += NCONV * 4) {
            const float* sp[4]; __half* dp[4]; int* fp[4]; bool ok[4];
            float4 vv[4][4];
            #pragma unroll
            for (int j = 0; j < 4; j++) {
                int u = i + j * NCONV;
                ok[j] = (u < NU);
                if (ok[j])
                    unit_decode(u, X, S, Wi, Ui, Wf, Uf, Wg, Ug, Wc, Uc,
                                &sp[j], &dp[j], &fp[j]);
            }
            #pragma unroll
            for (int j = 0; j < 4; j++)
                if (ok[j]) unit_load(sp[j], tid, vv[j]);
            #pragma unroll
            for (int j = 0; j < 4; j++)
                if (ok[j]) unit_store(dp[j], tid, vv[j]);
            __syncthreads();
            if (tid == 0) {
                asm volatile("membar.gl;" ::: "memory");
                #pragma unroll
                for (int j = 0; j < 4; j++)
                    if (ok[j]) atomicAdd(fp[j], 1);
            }
        }
        return;
    }

    // ================= GEMM CTAs (R10 core) =================
    const uint32_t sb = s2u(smem);
    const int gate = bid >> 6;
    const int bm   = ((bid >> 4) & 3) * BM;
    const int bn   = (bid & 15) * BN;
    const int g2   = gate * 2;

    // wait for prologue data: all acts + block 0 (kb 0-3) of phase-0 matrix
    wait_ge(&g_actsflag, NU_ACT);
    wait_ge(&g_wflag[g2 * 16 + 0], 128);

    const int warp = tid >> 5;
    const int lane = tid & 31;
    const int wm = warp >> 1;
    const int wn = warp & 1;
    const int lr  = lane & 15;
    const int lc8 = (lane >> 4) * 8;

    float acc[4][8][4];
    #pragma unroll
    for (int i = 0; i < 4; i++)
        #pragma unroll
        for (int j = 0; j < 8; j++)
            #pragma unroll
            for (int k = 0; k < 4; k++) acc[i][j][k] = 0.0f;

    uint32_t a_lane = (uint32_t)((wm * 64 + lr) * (A_STRIDE * 2) + lc8 * 2);
    uint32_t b_lane = (uint32_t)(lr * (B_STRIDE * 2) + (wn * 64 + lc8) * 2);

    prefetch(sb + 0 * STAGE_B, tid, gate, bm, bn, 0);
    asm volatile("cp.async.commit_group;" ::: "memory");
    prefetch(sb + 1 * STAGE_B, tid, gate, bm, bn, 1);
    asm volatile("cp.async.commit_group;" ::: "memory");
    prefetch(sb + 2 * STAGE_B, tid, gate, bm, bn, 2);
    asm volatile("cp.async.commit_group;" ::: "memory");

    // software-pipelined flag probe for the first wait point (cc=4 -> blk 1)
    int probe;
    {
        const int* f0 = &g_wflag[g2 * 16 + 1];
        asm volatile("ld.acquire.gpu.b32 %0, [%1];" : "=r"(probe) : "l"(f0));
    }

    #pragma unroll 1
    for (int c = 0; c < NITER; c++) {
        asm volatile("cp.async.wait_group 2;" ::: "memory");
        __syncthreads();

        int cc = c + 3;
        if (cc < NITER) {
            if ((cc & 3) == 0) {
                int m = g2 + (cc >> 6);
                int blk = (cc & 63) >> 2;
                if (probe < 128) wait_ge(&g_wflag[m * 16 + blk], 128);
                int ccn = cc + 4;
                if (ccn < NITER) {
                    int mn = g2 + (ccn >> 6);
                    int bkn = (ccn & 63) >> 2;
                    const int* fn = &g_wflag[mn * 16 + bkn];
                    asm volatile("ld.acquire.gpu.b32 %0, [%1];"
                                 : "=r"(probe) : "l"(fn));
                }
            }
            prefetch(sb + (uint32_t)(cc & 3) * STAGE_B, tid, gate, bm, bn, cc);
        }
        asm volatile("cp.async.commit_group;" ::: "memory");

        uint32_t st = sb + (uint32_t)(c & 3) * STAGE_B;
        #pragma unroll
        for (int kf = 0; kf < 2; kf++) {
            uint32_t aoff = st + OFF_A + a_lane + (uint32_t)(kf * 32);
            uint32_t boff = st + OFF_B + b_lane + (uint32_t)(kf * 16 * B_STRIDE * 2);

            uint32_t ar[4][4], br[4][4];
            #pragma unroll
            for (int mf = 0; mf < 4; mf++)
                LDSM4(ar[mf], aoff + (uint32_t)(mf * 16 * A_STRIDE * 2));
            #pragma unroll
            for (int nf2 = 0; nf2 < 4; nf2++)
                LDSM4T(br[nf2], boff + (uint32_t)(nf2 * 32));

            #pragma unroll
            for (int mf = 0; mf < 4; mf++)
                #pragma unroll
                for (int nf = 0; nf < 8; nf++)
                    MMA(acc[mf][nf], ar[mf], br[nf >> 1][(nf & 1) * 2],
                        br[nf >> 1][(nf & 1) * 2 + 1]);
        }
    }

    float* Zg = g_Z + (size_t)gate * BH;
    const int gr = lane >> 2;
    const int gc = (lane & 3) * 2;
    #pragma unroll
    for (int mf = 0; mf < 4; mf++) {
        #pragma unroll
        for (int nf = 0; nf < 8; nf++) {
            int row = bm + wm * 64 + mf * 16 + gr;
            int col = bn + wn * 64 + nf * 8 + gc;
            *reinterpret_cast<float2*>(&Zg[(size_t)row * HDIM + col]) =
                make_float2(acc[mf][nf][0], acc[mf][nf][1]);
            *reinterpret_cast<float2*>(&Zg[(size_t)(row + 8) * HDIM + col]) =
                make_float2(acc[mf][nf][2], acc[mf][nf][3]);
        }
    }
}

// ---------------- fused gate epilogue (R10 verbatim + flag reset) ----------
__device__ __forceinline__ float sigmoidf_(float x) {
    return 1.0f / (1.0f + __expf(-x));
}

__global__ void lstm_epilogue(const float* __restrict__ bi,
                              const float* __restrict__ bf,
                              const float* __restrict__ bg,
                              const float* __restrict__ bc,
                              const float* __restrict__ prevout,
                              float* __restrict__ out, int out_size) {
    // reset producer-consumer flags for next graph replay
    if (blockIdx.x == 0) {
        if (threadIdx.x < 128) g_wflag[threadIdx.x] = 0;
        if (threadIdx.x == 0) g_actsflag = 0;
    }

    int idx = (blockIdx.x * blockDim.x + threadIdx.x) * 4;
    if (idx >= BH) return;
    int h = idx & (HDIM - 1);

    float4 zi = *reinterpret_cast<const float4*>(&g_Z[0 * (size_t)BH + idx]);
    float4 zf = *reinterpret_cast<const float4*>(&g_Z[1 * (size_t)BH + idx]);
    float4 zg = *reinterpret_cast<const float4*>(&g_Z[2 * (size_t)BH + idx]);
    float4 zc = *reinterpret_cast<const float4*>(&g_Z[3 * (size_t)BH + idx]);
    float4 po = *reinterpret_cast<const float4*>(&prevout[idx]);
    float4 vbi = *reinterpret_cast<const float4*>(&bi[h]);
    float4 vbf = *reinterpret_cast<const float4*>(&bf[h]);
    float4 vbg = *reinterpret_cast<const float4*>(&bg[h]);
    float4 vbc = *reinterpret_cast<const float4*>(&bc[h]);

    float c4[4], s4[4];
    float zis[4] = {zi.x, zi.y, zi.z, zi.w};
    float zfs[4] = {zf.x, zf.y, zf.z, zf.w};
    float zgs[4] = {zg.x, zg.y, zg.z, zg.w};
    float zcs[4] = {zc.x, zc.y, zc.z, zc.w};
    float pos[4] = {po.x, po.y, po.z, po.w};
    float bis[4] = {vbi.x, vbi.y, vbi.z, vbi.w};
    float bfs[4] = {vbf.x, vbf.y, vbf.z, vbf.w};
    float bgs[4] = {vbg.x, vbg.y, vbg.z, vbg.w};
    float bcs[4] = {vbc.x, vbc.y, vbc.z, vbc.w};

    #pragma unroll
    for (int j = 0; j < 4; j++) {
        float ig = sigmoidf_(zis[j] + bis[j]);
        float fg = sigmoidf_(zfs[j] + bfs[j]);
        float gg = sigmoidf_(zgs[j] + bgs[j]);   // reference quirk: sigmoid for g
        float cc = tanhf(zcs[j] + bcs[j]);
        c4[j] = fg * pos[j] + ig * cc;
        s4[j] = gg * tanhf(c4[j]);
    }

    float4 cv = make_float4(c4[0], c4[1], c4[2], c4[3]);
    float4 sv = make_float4(s4[0], s4[1], s4[2], s4[3]);

    if (out_size >= 3 * BH) {
        *reinterpret_cast<float4*>(&out[idx])          = cv;
        *reinterpret_cast<float4*>(&out[BH + idx])     = sv;
        *reinterpret_cast<float4*>(&out[2 * BH + idx]) = cv;
    } else if (out_size >= 2 * BH) {
        *reinterpret_cast<float4*>(&out[idx])      = sv;
        *reinterpret_cast<float4*>(&out[BH + idx]) = cv;
    } else {
        *reinterpret_cast<float4*>(&out[idx]) = cv;
    }
}

// ---------------- launcher ----------------
extern "C" void kernel_launch(void* const* d_in, const int* in_sizes, int n_in,
                              void* d_out, int out_size) {
    const float* inputs = (const float*)d_in[0];
    const float* states = (const float*)d_in[1];
    const float* Wi = (const float*)d_in[2];
    const float* Ui = (const float*)d_in[3];
    const float* bi = (const float*)d_in[4];
    const float* Wf = (const float*)d_in[5];
    const float* Uf = (const float*)d_in[6];
    const float* bf = (const float*)d_in[7];
    const float* Wg = (const float*)d_in[8];
    const float* Ug = (const float*)d_in[9];
    const float* bg = (const float*)d_in[10];
    const float* Wc = (const float*)d_in[11];
    const float* Uc = (const float*)d_in[12];
    const float* bc = (const float*)d_in[13];

    const float* prevstate = states;        // states[0]
    const float* prevout   = states + BH;   // states[1]

    cudaFuncSetAttribute(gemm_fused, cudaFuncAttributeMaxDynamicSharedMemorySize,
                         DYN_SMEM);

    gemm_fused<<<NGEMM + NCONV, 128, DYN_SMEM>>>(inputs, prevstate,
                                                 Wi, Ui, Wf, Uf, Wg, Ug, Wc, Uc);

    lstm_epilogue<<<BH / (256 * 4), 256>>>(bi, bf, bg, bc, prevout,
                                           (float*)d_out, out_size);
}

// round 14
// speedup vs baseline: 2.1537x; 2.1537x over previous
#include <cuda_runtime.h>
#include <cuda_fp16.h>
#include <math.h>
#include <stdint.h>

// ---------------- problem constants ----------------
#define BATCH 512
#define HDIM  2048
#define BH    (BATCH * HDIM)       // 1,048,576
#define ACT   (BATCH * HDIM)
#define WELEM (2048 * 2048)
#define KTOT  4096

// ---------------- GEMM tiling (proven R10 config) ----------------
#define BM 128
#define BN 128
#define BK 32
#define NITER (KTOT / BK)          // 128

#define A_STRIDE 40
#define B_STRIDE 136
#define A_TILE_B (128 * A_STRIDE * 2)   // 10240 B
#define B_TILE_B (BK * B_STRIDE * 2)    // 8704 B
#define OFF_A 0
#define OFF_B (A_TILE_B)
#define STAGE_B (A_TILE_B + B_TILE_B)   // 18944
#define NSTAGE 4
#define DYN_SMEM (NSTAGE * STAGE_B)     // 75776

// ---------------- device scratch ----------------
__device__ float g_Z[4ull * BH];                 // 16 MB
__device__ __half g_A[2ull * ACT];               // [phase][B][2048] fp16
__device__ __half g_B[8ull * WELEM];             // [gate*2+phase][K][N] fp16

// ---------------- PTX helpers ----------------
__device__ __forceinline__ uint32_t s2u(const void* p) {
    uint32_t a;
    asm("{ .reg .u64 t; cvta.to.shared.u64 t, %1; cvt.u32.u64 %0, t; }"
        : "=r"(a) : "l"(p));
    return a;
}
__device__ __forceinline__ void cp16(uint32_t dst, const void* src) {
    asm volatile("cp.async.cg.shared.global [%0], [%1], 16;" :: "r"(dst), "l"(src));
}
#define LDSM4(R, addr)                                                        \
    asm volatile("ldmatrix.sync.aligned.m8n8.x4.shared.b16 {%0,%1,%2,%3}, [%4];" \
                 : "=r"((R)[0]), "=r"((R)[1]), "=r"((R)[2]), "=r"((R)[3])     \
                 : "r"(addr))
#define LDSM4T(R, addr)                                                       \
    asm volatile("ldmatrix.sync.aligned.m8n8.x4.trans.shared.b16 {%0,%1,%2,%3}, [%4];" \
                 : "=r"((R)[0]), "=r"((R)[1]), "=r"((R)[2]), "=r"((R)[3])     \
                 : "r"(addr))
#define MMA(D, A, B0, B1)                                                     \
    asm volatile("mma.sync.aligned.m16n8k16.row.col.f32.f16.f16.f32 "          \
                 "{%0,%1,%2,%3},{%4,%5,%6,%7},{%8,%9},{%0,%1,%2,%3};"          \
                 : "+f"((D)[0]), "+f"((D)[1]), "+f"((D)[2]), "+f"((D)[3])     \
                 : "r"((A)[0]), "r"((A)[1]), "r"((A)[2]), "r"((A)[3]),        \
                   "r"(B0), "r"(B1))

// ---------------- merged conversion kernel (16 floats/thread, MLP=4) -------
// grid (1024, 9): y<8 -> weight matrix y; y==8, x<512 -> activations
__device__ __forceinline__ void cvt16_store(const float* __restrict__ src,
                                            __half* __restrict__ dst) {
    // 4 front-batched LDG.128 (MLP=4), then 2 uint4 stores
    float4 v0 = *reinterpret_cast<const float4*>(src);
    float4 v1 = *reinterpret_cast<const float4*>(src + 4);
    float4 v2 = *reinterpret_cast<const float4*>(src + 8);
    float4 v3 = *reinterpret_cast<const float4*>(src + 12);
    __half2 h[8];
    h[0] = __floats2half2_rn(v0.x, v0.y);
    h[1] = __floats2half2_rn(v0.z, v0.w);
    h[2] = __floats2half2_rn(v1.x, v1.y);
    h[3] = __floats2half2_rn(v1.z, v1.w);
    h[4] = __floats2half2_rn(v2.x, v2.y);
    h[5] = __floats2half2_rn(v2.z, v2.w);
    h[6] = __floats2half2_rn(v3.x, v3.y);
    h[7] = __floats2half2_rn(v3.z, v3.w);
    uint4* q = reinterpret_cast<uint4*>(dst);
    q[0] = *reinterpret_cast<uint4*>(&h[0]);
    q[1] = *reinterpret_cast<uint4*>(&h[4]);
}

__global__ void convert_all(const float* __restrict__ X,
                            const float* __restrict__ S,
                            const float* Wi, const float* Ui,
                            const float* Wf, const float* Uf,
                            const float* Wg, const float* Ug,
                            const float* Wc, const float* Uc) {
    int mat = blockIdx.y;
    if (mat == 8) {
        if (blockIdx.x >= 512) return;
        size_t base = ((size_t)blockIdx.x * 256 + threadIdx.x) * 16;
        const float* src = (base < ACT) ? (X + base) : (S + (base - ACT));
        cvt16_store(src, &g_A[base]);
        return;
    }
    const float* src;
    switch (mat) {
        case 0: src = Wi; break; case 1: src = Ui; break;
        case 2: src = Wf; break; case 3: src = Uf; break;
        case 4: src = Wg; break; case 5: src = Ug; break;
        case 6: src = Wc; break; default: src = Uc; break;
    }
    size_t base = ((size_t)blockIdx.x * blockDim.x + threadIdx.x) * 16;
    cvt16_store(src + base, &g_B[(size_t)mat * WELEM + base]);
}

// ---------------- mma.sync GEMM (R10 verbatim) ----------------
__device__ __forceinline__ void prefetch(uint32_t stage, int tid,
                                         int gate, int bm, int bn, int c) {
    int k0 = c * BK;
    int phase = k0 >> 11;
    int kk = k0 & 2047;
    const __half* A_p = g_A + (size_t)phase * ACT + (size_t)bm * 2048 + kk;
    const __half* B_p = g_B + (size_t)(gate * 2 + phase) * WELEM
                            + (size_t)kk * 2048 + bn;

    #pragma unroll
    for (int t = 0; t < 4; t++) {
        int cid = tid + t * 128;
        int r = cid >> 2, cc = cid & 3;
        cp16(stage + OFF_A + (uint32_t)(r * (A_STRIDE * 2) + cc * 16),
             A_p + (size_t)r * 2048 + cc * 8);
    }
    #pragma unroll
    for (int t = 0; t < 4; t++) {
        int cid = tid + t * 128;
        int r = cid >> 4, cc = cid & 15;
        cp16(stage + OFF_B + (uint32_t)(r * (B_STRIDE * 2) + cc * 16),
             B_p + (size_t)r * 2048 + cc * 8);
    }
}

__global__ __launch_bounds__(128, 2) void gemm_mma() {
    extern __shared__ char smem[];
    const uint32_t sb = s2u(smem);
    const int tid  = threadIdx.x;
    const int gate = blockIdx.z;
    const int bm   = blockIdx.y * BM;
    const int bn   = blockIdx.x * BN;

    const int warp = tid >> 5;
    const int lane = tid & 31;
    const int wm = warp >> 1;
    const int wn = warp & 1;
    const int lr  = lane & 15;
    const int lc8 = (lane >> 4) * 8;

    float acc[4][8][4];
    #pragma unroll
    for (int i = 0; i < 4; i++)
        #pragma unroll
        for (int j = 0; j < 8; j++)
            #pragma unroll
            for (int k = 0; k < 4; k++) acc[i][j][k] = 0.0f;

    uint32_t a_lane = (uint32_t)((wm * 64 + lr) * (A_STRIDE * 2) + lc8 * 2);
    uint32_t b_lane = (uint32_t)(lr * (B_STRIDE * 2) + (wn * 64 + lc8) * 2);

    prefetch(sb + 0 * STAGE_B, tid, gate, bm, bn, 0);
    asm volatile("cp.async.commit_group;" ::: "memory");
    prefetch(sb + 1 * STAGE_B, tid, gate, bm, bn, 1);
    asm volatile("cp.async.commit_group;" ::: "memory");
    prefetch(sb + 2 * STAGE_B, tid, gate, bm, bn, 2);
    asm volatile("cp.async.commit_group;" ::: "memory");

    #pragma unroll 1
    for (int c = 0; c < NITER; c++) {
        asm volatile("cp.async.wait_group 2;" ::: "memory");
        __syncthreads();

        if (c + 3 < NITER)
            prefetch(sb + (uint32_t)((c + 3) & 3) * STAGE_B, tid, gate, bm, bn, c + 3);
        asm volatile("cp.async.commit_group;" ::: "memory");

        uint32_t st = sb + (uint32_t)(c & 3) * STAGE_B;
        #pragma unroll
        for (int kf = 0; kf < 2; kf++) {
            uint32_t aoff = st + OFF_A + a_lane + (uint32_t)(kf * 32);
            uint32_t boff = st + OFF_B + b_lane + (uint32_t)(kf * 16 * B_STRIDE * 2);

            uint32_t ar[4][4], br[4][4];
            #pragma unroll
            for (int mf = 0; mf < 4; mf++)
                LDSM4(ar[mf], aoff + (uint32_t)(mf * 16 * A_STRIDE * 2));
            #pragma unroll
            for (int nf2 = 0; nf2 < 4; nf2++)
                LDSM4T(br[nf2], boff + (uint32_t)(nf2 * 32));

            #pragma unroll
            for (int mf = 0; mf < 4; mf++)
                #pragma unroll
                for (int nf = 0; nf < 8; nf++)
                    MMA(acc[mf][nf], ar[mf], br[nf >> 1][(nf & 1) * 2],
                        br[nf >> 1][(nf & 1) * 2 + 1]);
        }
    }

    float* Zg = g_Z + (size_t)gate * BH;
    const int gr = lane >> 2;
    const int gc = (lane & 3) * 2;
    #pragma unroll
    for (int mf = 0; mf < 4; mf++) {
        #pragma unroll
        for (int nf = 0; nf < 8; nf++) {
            int row = bm + wm * 64 + mf * 16 + gr;
            int col = bn + wn * 64 + nf * 8 + gc;
            *reinterpret_cast<float2*>(&Zg[(size_t)row * HDIM + col]) =
                make_float2(acc[mf][nf][0], acc[mf][nf][1]);
            *reinterpret_cast<float2*>(&Zg[(size_t)(row + 8) * HDIM + col]) =
                make_float2(acc[mf][nf][2], acc[mf][nf][3]);
        }
    }
}

// ---------------- fused gate epilogue (streaming loads/stores) -------------
__device__ __forceinline__ float sigmoidf_(float x) {
    return 1.0f / (1.0f + __expf(-x));
}

__global__ void lstm_epilogue(const float* __restrict__ bi,
                              const float* __restrict__ bf,
                              const float* __restrict__ bg,
                              const float* __restrict__ bc,
                              const float* __restrict__ prevout,
                              float* __restrict__ out, int out_size) {
    int idx = (blockIdx.x * blockDim.x + threadIdx.x) * 4;
    if (idx >= BH) return;
    int h = idx & (HDIM - 1);

    // single-use data: evict-first streaming loads
    float4 zi = __ldcs(reinterpret_cast<const float4*>(&g_Z[0 * (size_t)BH + idx]));
    float4 zf = __ldcs(reinterpret_cast<const float4*>(&g_Z[1 * (size_t)BH + idx]));
    float4 zg = __ldcs(reinterpret_cast<const float4*>(&g_Z[2 * (size_t)BH + idx]));
    float4 zc = __ldcs(reinterpret_cast<const float4*>(&g_Z[3 * (size_t)BH + idx]));
    float4 po = __ldcs(reinterpret_cast<const float4*>(&prevout[idx]));
    float4 vbi = *reinterpret_cast<const float4*>(&bi[h]);
    float4 vbf = *reinterpret_cast<const float4*>(&bf[h]);
    float4 vbg = *reinterpret_cast<const float4*>(&bg[h]);
    float4 vbc = *reinterpret_cast<const float4*>(&bc[h]);

    float c4[4], s4[4];
    float zis[4] = {zi.x, zi.y, zi.z, zi.w};
    float zfs[4] = {zf.x, zf.y, zf.z, zf.w};
    float zgs[4] = {zg.x, zg.y, zg.z, zg.w};
    float zcs[4] = {zc.x, zc.y, zc.z, zc.w};
    float pos[4] = {po.x, po.y, po.z, po.w};
    float bis[4] = {vbi.x, vbi.y, vbi.z, vbi.w};
    float bfs[4] = {vbf.x, vbf.y, vbf.z, vbf.w};
    float bgs[4] = {vbg.x, vbg.y, vbg.z, vbg.w};
    float bcs[4] = {vbc.x, vbc.y, vbc.z, vbc.w};

    #pragma unroll
    for (int j = 0; j < 4; j++) {
        float ig = sigmoidf_(zis[j] + bis[j]);
        float fg = sigmoidf_(zfs[j] + bfs[j]);
        float gg = sigmoidf_(zgs[j] + bgs[j]);   // reference quirk: sigmoid for g
        float cc = tanhf(zcs[j] + bcs[j]);
        c4[j] = fg * pos[j] + ig * cc;
        s4[j] = gg * tanhf(c4[j]);
    }

    float4 cv = make_float4(c4[0], c4[1], c4[2], c4[3]);
    float4 sv = make_float4(s4[0], s4[1], s4[2], s4[3]);

    if (out_size >= 3 * BH) {
        __stcs(reinterpret_cast<float4*>(&out[idx]),          cv);
        __stcs(reinterpret_cast<float4*>(&out[BH + idx]),     sv);
        __stcs(reinterpret_cast<float4*>(&out[2 * BH + idx]), cv);
    } else if (out_size >= 2 * BH) {
        __stcs(reinterpret_cast<float4*>(&out[idx]),      sv);
        __stcs(reinterpret_cast<float4*>(&out[BH + idx]), cv);
    } else {
        __stcs(reinterpret_cast<float4*>(&out[idx]), cv);
    }
}

// ---------------- launcher ----------------
extern "C" void kernel_launch(void* const* d_in, const int* in_sizes, int n_in,
                              void* d_out, int out_size) {
    const float* inputs = (const float*)d_in[0];
    const float* states = (const float*)d_in[1];
    const float* Wi = (const float*)d_in[2];
    const float* Ui = (const float*)d_in[3];
    const float* bi = (const float*)d_in[4];
    const float* Wf = (const float*)d_in[5];
    const float* Uf = (const float*)d_in[6];
    const float* bf = (const float*)d_in[7];
    const float* Wg = (const float*)d_in[8];
    const float* Ug = (const float*)d_in[9];
    const float* bg = (const float*)d_in[10];
    const float* Wc = (const float*)d_in[11];
    const float* Uc = (const float*)d_in[12];
    const float* bc = (const float*)d_in[13];

    const float* prevstate = states;        // states[0]
    const float* prevout   = states + BH;   // states[1]

    cudaFuncSetAttribute(gemm_mma, cudaFuncAttributeMaxDynamicSharedMemorySize,
                         DYN_SMEM);

    dim3 cgrid(WELEM / (256 * 16), 9);   // (1024, 9): 8 weights + acts
    convert_all<<<cgrid, 256>>>(inputs, prevstate,
                                Wi, Ui, Wf, Uf, Wg, Ug, Wc, Uc);

    dim3 ggrid(HDIM / BN, BATCH / BM, 4);   // (16, 4, 4) = 256 CTAs
    gemm_mma<<<ggrid, 128, DYN_SMEM>>>();

    lstm_epilogue<<<BH / (256 * 4), 256>>>(bi, bf, bg, bc, prevout,
                                           (float*)d_out, out_size);
}